// round 3
// baseline (speedup 1.0000x reference)
#include <cuda_runtime.h>
#include <cstdint>

// RoPE3DEncoder: T=32, H=64, W=64, DIM=192 (DIM_X=DIM_Y=DIM_T=64).
// Single 64-pos x 64-col cos/sin table (compile-time) covers all axes.
// Output: cos [131072 x 192] f32, then sin. For fixed (t,h), rows w=0..63
// form a 48KB contiguous block. Each CTA stages one such block (cos OR sin)
// in SMEM and emits it with ONE cp.async.bulk store, bypassing the
// per-SM L1/LSU store pipeline identified as the bottleneck.

#define NQ (131072 * 48)          // float4 quads per table

// ---------------- compile-time math ----------------
constexpr double K_PI  = 3.14159265358979323846264338327950288;
constexpr double K_LN2 = 0.69314718055994530941723212145818;

constexpr double cexp(double x) {
    int n = 0; double y = x;
    while (y < -0.35) { y += K_LN2; n--; }
    while (y >  0.35) { y -= K_LN2; n++; }
    double term = 1.0, s = 1.0;
    for (int i = 1; i < 26; i++) { term *= y / i; s += term; }
    while (n < 0) { s *= 0.5; n++; }
    while (n > 0) { s *= 2.0; n--; }
    return s;
}
constexpr double csin(double x) {
    double tp = 2.0 * K_PI;
    long long k = (long long)(x / tp + 0.5);
    double y = x - (double)k * tp;
    double y2 = y * y, term = y, s = y;
    for (int i = 1; i < 16; i++) {
        term *= -y2 / (double)((2 * i) * (2 * i + 1));
        s += term;
    }
    return s;
}
constexpr double ccos(double x) { return csin(x + K_PI * 0.5); }

struct alignas(16) Tab { float c[64 * 64]; float s[64 * 64]; };

constexpr Tab make_tab() {
    Tab t{};
    for (int pos = 0; pos < 64; pos++) {
        for (int j = 0; j < 32; j++) {
            float invf = (float)cexp(-9.210340371976184 * (double)j / 32.0);
            float ang  = (float)pos * invf;       // match reference f32 pipeline
            float cv = (float)ccos((double)ang);
            float sv = (float)csin((double)ang);
            t.c[pos * 64 + j]      = cv;
            t.c[pos * 64 + j + 32] = cv;
            t.s[pos * 64 + j]      = sv;
            t.s[pos * 64 + j + 32] = sv;
        }
    }
    return t;
}

constexpr Tab H_TAB = make_tab();
__device__ const Tab g_tab = H_TAB;

// ---------------- fill kernel ----------------
// grid = 4096: b&1 selects cos/sin table, pair = b>>1 in [0,2048),
// t = pair>>6, h = pair&63. 48KB dynamic SMEM block = 3072 float4 quads
// (64 w-rows x 48 quads: [X(w):16 | Y(h):16 | T(t):16]).
__global__ void __launch_bounds__(256) rope_fill_bulk(float* __restrict__ out) {
    extern __shared__ float4 smem[];          // 3072 quads = 48KB

    unsigned b    = blockIdx.x;
    unsigned s    = b & 1u;                   // 0 = cos, 1 = sin
    unsigned pair = b >> 1;                   // t*64 + h
    unsigned t    = pair >> 6;
    unsigned h    = pair & 63u;
    unsigned tid  = threadIdx.x;

    const float4* tab = reinterpret_cast<const float4*>(s ? g_tab.s : g_tab.c);

    #pragma unroll
    for (int p = (int)tid; p < 3072; p += 256) {
        unsigned w = (unsigned)p / 48u;
        unsigned q = (unsigned)p - w * 48u;
        unsigned idx = (q < 16u) ? (w * 16u + q)
                     : (q < 32u) ? (h * 16u + (q - 16u))
                                 : (t * 16u + (q - 32u));
        smem[p] = tab[idx];
    }
    __syncthreads();
    // Order generic-proxy STS before async-proxy bulk read.
    asm volatile("fence.proxy.async.shared::cta;" ::: "memory");

    if (tid == 0) {
        uint32_t saddr = (uint32_t)__cvta_generic_to_shared(smem);
        uint64_t gaddr = (uint64_t)out
                       + (uint64_t)pair * (48u * 1024u)
                       + (uint64_t)s * ((uint64_t)NQ * 16u);
        uint32_t nbytes = 48u * 1024u;
        asm volatile(
            "cp.async.bulk.global.shared::cta.bulk_group [%0], [%1], %2;"
            :: "l"(gaddr), "r"(saddr), "r"(nbytes) : "memory");
        asm volatile("cp.async.bulk.commit_group;" ::: "memory");
        asm volatile("cp.async.bulk.wait_group 0;" ::: "memory");
    }
}

extern "C" void kernel_launch(void* const* d_in, const int* in_sizes, int n_in,
                              void* d_out, int out_size) {
    (void)d_in; (void)in_sizes; (void)n_in; (void)out_size;
    rope_fill_bulk<<<4096, 256, 48 * 1024>>>(reinterpret_cast<float*>(d_out));
}

// round 4
// speedup vs baseline: 1.1979x; 1.1979x over previous
#include <cuda_runtime.h>

// RoPE3DEncoder: T=32, H=64, W=64, DIM=192 (DIM_X=DIM_Y=DIM_T=64).
// Single 64-pos x 64-col cos/sin table (compile-time constexpr) covers all
// three axes. Output: cos [131072 x 192] f32 followed by sin.
// Pure write-stream kernel; stores use .cs (streaming, evict-first) since
// every output line is written once and never read -> avoid L2 dirty-line
// churn across graph replays.

#define ROWS 131072               // 32*64*64
#define NQ   (ROWS * 48)          // float4 quads per table

// ---------------- compile-time math ----------------
constexpr double K_PI  = 3.14159265358979323846264338327950288;
constexpr double K_LN2 = 0.69314718055994530941723212145818;

constexpr double cexp(double x) {
    int n = 0; double y = x;
    while (y < -0.35) { y += K_LN2; n--; }
    while (y >  0.35) { y -= K_LN2; n++; }
    double term = 1.0, s = 1.0;
    for (int i = 1; i < 26; i++) { term *= y / i; s += term; }
    while (n < 0) { s *= 0.5; n++; }
    while (n > 0) { s *= 2.0; n--; }
    return s;
}
constexpr double csin(double x) {
    double tp = 2.0 * K_PI;
    long long k = (long long)(x / tp + 0.5);
    double y = x - (double)k * tp;
    double y2 = y * y, term = y, s = y;
    for (int i = 1; i < 16; i++) {
        term *= -y2 / (double)((2 * i) * (2 * i + 1));
        s += term;
    }
    return s;
}
constexpr double ccos(double x) { return csin(x + K_PI * 0.5); }

struct alignas(16) Tab { float c[64 * 64]; float s[64 * 64]; };

constexpr Tab make_tab() {
    Tab t{};
    for (int pos = 0; pos < 64; pos++) {
        for (int j = 0; j < 32; j++) {
            float invf = (float)cexp(-9.210340371976184 * (double)j / 32.0);
            float ang  = (float)pos * invf;       // match reference f32 pipeline
            float cv = (float)ccos((double)ang);
            float sv = (float)csin((double)ang);
            t.c[pos * 64 + j]      = cv;
            t.c[pos * 64 + j + 32] = cv;
            t.s[pos * 64 + j]      = sv;
            t.s[pos * 64 + j + 32] = sv;
        }
    }
    return t;
}

constexpr Tab H_TAB = make_tab();
__device__ const Tab g_tab = H_TAB;

// ---------------- fill kernel (R1 structure + streaming stores) ----------
__global__ void __launch_bounds__(256) rope_fill(float4* __restrict__ out) {
    unsigned idx = blockIdx.x * blockDim.x + threadIdx.x;   // quad index
    unsigned row = idx / 48u;
    unsigned q   = idx - row * 48u;
    unsigned c4  = q * 4u;                 // starting column of this quad

    unsigned w = row & 63u;
    unsigned h = (row >> 6) & 63u;
    unsigned t = row >> 12;

    // Quads never straddle the 64/128 axis boundaries.
    unsigned pos = (c4 < 64u) ? w : ((c4 < 128u) ? h : t);
    unsigned off = (pos * 64u + (c4 & 63u)) >> 2;   // quad offset

    float4 vc = reinterpret_cast<const float4*>(g_tab.c)[off];
    float4 vs = reinterpret_cast<const float4*>(g_tab.s)[off];

    __stcs(out + idx,      vc);   // cos half, streaming
    __stcs(out + NQ + idx, vs);   // sin half, streaming
}

extern "C" void kernel_launch(void* const* d_in, const int* in_sizes, int n_in,
                              void* d_out, int out_size) {
    (void)d_in; (void)in_sizes; (void)n_in; (void)out_size;
    rope_fill<<<NQ / 256, 256>>>(reinterpret_cast<float4*>(d_out));
}